// round 14
// baseline (speedup 1.0000x reference)
#include <cuda_runtime.h>

// 3D SSIM, B=4, 128^3, WIN=7 separable box -> 122^3, mean.
// Intermediate: ONE float4 per voxel (sx, sy, sxx+syy, sxy), pitch 128.
// Kernel A: R8 fused W+H window sums (staged, 16-wide W chunks, H reg-ring).
// Kernel B: D window sums with SMEM ring, 6 blocks/SM (42-reg cap), paired-div
//           SSIM, fused deterministic reduce.

#define BATCH 4
#define DD 128
#define HH 128
#define WW 128
#define WO  122
#define WIN 7

#define STRIP  14
#define NSTRIP 9
#define XP 132
#define RP 123
#define GP 128            // g2 row pitch (elements)

// g2 rows: (b,d,h) = 4*128*122 = 62,464 rows, pitch 128 float4 -> 128 MB.
__device__ float4 g2q[62464 * GP];
__device__ double g_part[2048];
__device__ unsigned int g_ctr = 0;

// ---------------------------------------------------------------------------
// Kernel A: fused W+H box sums, 4-quantity pack (exact R8).
// grid = b(4)*d(128)*strip(9) = 4608 blocks, 256 threads, smem 60,480 B.
// ---------------------------------------------------------------------------
__global__ void __launch_bounds__(256, 3)
fused_wh(const float* __restrict__ X, const float* __restrict__ Y) {
    extern __shared__ float sm[];
    float*  xs  = sm;                         // [20][XP]
    float*  ys  = sm + 20 * XP;               // [20][XP]
    float4* rw4 = (float4*)(sm + 40 * XP);    // [20][RP]

    const int s  = blockIdx.x % NSTRIP;
    const int d  = (blockIdx.x / NSTRIP) % DD;
    const int b  = blockIdx.x / (NSTRIP * DD);
    const int h0 = s * STRIP;
    const int nout = min(STRIP, WO - h0);     // 14 (last strip: 10)
    const int nin  = nout + 6;                // 20 (last strip: 16)
    const int tid  = threadIdx.x;

    const size_t gbase = ((size_t)(b * DD + d) * HH + h0) * WW;
    for (int i = tid; i < nin * 32; i += 256) {
        const int r = i >> 5, v = (i & 31) << 2;
        const float4 xv = *(const float4*)(X + gbase + (size_t)r * WW + v);
        const float4 yv = *(const float4*)(Y + gbase + (size_t)r * WW + v);
        *(float4*)(xs + r * XP + v) = xv;
        *(float4*)(ys + r * XP + v) = yv;
    }
    __syncthreads();

    // --- W-direction sliding sums: (sx, sy, sxx+syy, sxy) ---
    {
        const int njobs = nin * 8;
        for (int job = tid; job < njobs; job += 256) {
            const int r   = job % nin;
            const int ch  = job / nin;
            const int wst = ch * 16;
            const int nw  = (ch == 7) ? 10 : 16;

            float xv[24], yv[24];
#pragma unroll
            for (int k = 0; k < 6; k++) {
                if (wst + 4 * k < WW) {
                    const float4 xq = *(const float4*)(xs + r * XP + wst + 4 * k);
                    const float4 yq = *(const float4*)(ys + r * XP + wst + 4 * k);
                    xv[4*k] = xq.x; xv[4*k+1] = xq.y; xv[4*k+2] = xq.z; xv[4*k+3] = xq.w;
                    yv[4*k] = yq.x; yv[4*k+1] = yq.y; yv[4*k+2] = yq.z; yv[4*k+3] = yq.w;
                } else {
#pragma unroll
                    for (int u = 0; u < 4; u++) { xv[4*k+u] = 0.f; yv[4*k+u] = 0.f; }
                }
            }

            float s0 = 0.f, s1 = 0.f, s2 = 0.f, s4 = 0.f;
#pragma unroll
            for (int j = 0; j < 6; j++) {
                s0 += xv[j]; s1 += yv[j];
                s2 += xv[j] * xv[j] + yv[j] * yv[j];
                s4 += xv[j] * yv[j];
            }
#pragma unroll
            for (int o = 0; o < 16; o++) {
                if (o < nw) {
                    s0 += xv[o + 6]; s1 += yv[o + 6];
                    s2 += xv[o + 6] * xv[o + 6] + yv[o + 6] * yv[o + 6];
                    s4 += xv[o + 6] * yv[o + 6];
                    rw4[r * RP + wst + o] = make_float4(s0, s1, s2, s4);
                    s0 -= xv[o]; s1 -= yv[o];
                    s2 -= xv[o] * xv[o] + yv[o] * yv[o];
                    s4 -= xv[o] * yv[o];
                }
            }
        }
    }
    __syncthreads();

    // --- H-direction sliding sums with 7-deep register history ---
    for (int w = tid; w < WO; w += 256) {
        const size_t obase = ((size_t)(b * DD + d) * WO + h0) * GP + w;
        float4 hist[7];
        float4 acc = make_float4(0.f, 0.f, 0.f, 0.f);
#pragma unroll
        for (int r = 0; r < 20; r++) {
            if (r < nin) {
                const float4 v = rw4[r * RP + w];
                acc.x += v.x; acc.y += v.y; acc.z += v.z; acc.w += v.w;
                if (r >= 6) {
                    const int o = r - 6;
                    g2q[obase + (size_t)o * GP] = acc;
                    const float4 h7 = hist[o % 7];
                    acc.x -= h7.x; acc.y -= h7.y; acc.z -= h7.z; acc.w -= h7.w;
                }
                hist[r % 7] = v;
            }
        }
    }
}

// ---------------------------------------------------------------------------
// Kernel B: branch-free D window sums + SSIM (SMEM ring, paired division).
// ---------------------------------------------------------------------------
template <int NST>
__device__ __forceinline__ float run_chunk(size_t base, float C1, float C2,
                                           float4* ring) {
    constexpr float inv = 1.0f / 343.0f;
    constexpr float cov = 343.0f / 342.0f;
    const size_t ds = (size_t)WO * GP;

    float4 acc = make_float4(0.f, 0.f, 0.f, 0.f);
    float  local = 0.f;
    float  pn = 0.f, pd = 1.f;

#pragma unroll
    for (int j = 0; j < NST; j++) {
        const float4 v = __ldg(&g2q[base + (size_t)j * ds]);
        acc.x += v.x; acc.y += v.y; acc.z += v.z; acc.w += v.w;
        if (j >= 6) {
            const float ux  = acc.x * inv;      // mean x
            const float uy  = acc.y * inv;      // mean y
            const float uss = acc.z * inv;      // mean (x^2 + y^2)
            const float uxy = acc.w * inv;      // mean xy
            const float sq  = ux * ux + uy * uy;
            const float vxy = cov * (uxy - ux * uy);
            const float vs  = cov * (uss - sq);           // vx + vy
            const float A1 = 2.f * ux * uy + C1;
            const float A2 = 2.f * vxy + C2;
            const float B1 = sq + C1;
            const float B2 = vs + C2;
            const float n  = A1 * A2;
            const float dn = B1 * B2;
            if (((j - 6) & 1) == 0) {
                pn = n; pd = dn;
            } else {
                local += __fdividef(n * pd + pn * dn, dn * pd);
            }
            const float4 o4 = ring[(j - 6) % 7];   // written 6 steps ago
            acc.x -= o4.x; acc.y -= o4.y; acc.z -= o4.z; acc.w -= o4.w;
        }
        ring[j % 7] = v;
    }
    return local;
}

__global__ void __launch_bounds__(256, 6)
pass_d_ssim(const float* __restrict__ dr, float* __restrict__ out) {
    __shared__ float4 ringbuf[256 * 7];   // 28,672 B; per-thread stride 7 (28 words)
    __shared__ double red[256];

    const int tid   = threadIdx.x;
    const int idx   = blockIdx.x * 256 + tid;
    const int total = 8 * BATCH * WO * WO;

    float4* ring = &ringbuf[tid * 7];

    float local = 0.f;
    if (idx < total) {
        const int w = idx % WO;
        const int h = (idx / WO) % WO;
        const int b = (idx / (WO * WO)) % BATCH;
        const int c = idx / (WO * WO * BATCH);

        const int d0 = c * 16;                 // chunks 0..6: 16 outs, chunk 7: 10

        const float r  = __ldg(&dr[b]);
        const float C1 = (0.01f * r) * (0.01f * r);
        const float C2 = (0.03f * r) * (0.03f * r);

        const size_t base = ((size_t)(b * DD + d0) * WO + h) * GP + w;

        if (c < 7) local = run_chunk<22>(base, C1, C2, ring);   // 16 outputs
        else       local = run_chunk<16>(base, C1, C2, ring);   // 10 outputs
    }

    red[tid] = (double)local;
    __syncthreads();
#pragma unroll
    for (int s = 128; s > 0; s >>= 1) {
        if (tid < s) red[tid] += red[tid + s];
        __syncthreads();
    }

    __shared__ bool is_last;
    if (tid == 0) {
        g_part[blockIdx.x] = red[0];
        __threadfence();
        const unsigned int t = atomicAdd(&g_ctr, 1u);
        is_last = (t == gridDim.x - 1);
    }
    __syncthreads();

    if (is_last) {
        __threadfence();
        double v = 0.0;
        for (int i = tid; i < (int)gridDim.x; i += 256) v += g_part[i];
        red[tid] = v;
        __syncthreads();
#pragma unroll
        for (int s = 128; s > 0; s >>= 1) {
            if (tid < s) red[tid] += red[tid + s];
            __syncthreads();
        }
        if (tid == 0) {
            const double cnt = (double)BATCH * WO * WO * WO;
            out[0] = (float)(red[0] / cnt);
            atomicExch(&g_ctr, 0u);   // reset for next graph replay
        }
    }
}

extern "C" void kernel_launch(void* const* d_in, const int* in_sizes, int n_in,
                              void* d_out, int out_size) {
    const float* X  = (const float*)d_in[0];
    const float* Y  = (const float*)d_in[1];
    const float* dr = (const float*)d_in[2];
    float* out = (float*)d_out;

    const int smemA = (40 * XP) * (int)sizeof(float) + 20 * RP * (int)sizeof(float4); // 60,480 B
    cudaFuncSetAttribute(fused_wh, cudaFuncAttributeMaxDynamicSharedMemorySize, smemA);

    fused_wh<<<BATCH * DD * NSTRIP, 256, smemA>>>(X, Y);

    const int totalB = 8 * BATCH * WO * WO;          // 476,288
    const int nblocksB = (totalB + 255) / 256;       // 1861
    pass_d_ssim<<<nblocksB, 256>>>(dr, out);
}

// round 15
// speedup vs baseline: 1.3487x; 1.3487x over previous
#include <cuda_runtime.h>

// 3D SSIM, B=4, 128^3, WIN=7 separable box -> 122^3, mean.
// Intermediate: ONE float4 per voxel (sx, sy, sxx+syy, sxy), pitch 128.
// Kernel A: fused W+H window sums, STRIP=12 -> 54.4 KB smem -> 4 blocks/SM (real).
// Kernel B: R13 D window sums (SMEM ring, 5 blk/SM), paired-div SSIM, fused reduce.

#define BATCH 4
#define DD 128
#define HH 128
#define WW 128
#define WO  122
#define WIN 7

#define STRIP  12
#define NSTRIP 11         // 10 strips of 12 + last strip of 2
#define NIN    18         // STRIP + 6
#define XP 132
#define RP 123
#define GP 128            // g2 row pitch (elements)

// g2 rows: (b,d,h) = 4*128*122 = 62,464 rows, pitch 128 float4 -> 128 MB.
__device__ float4 g2q[62464 * GP];
__device__ double g_part[2048];
__device__ unsigned int g_ctr = 0;

// ---------------------------------------------------------------------------
// Kernel A: fused W+H box sums, 4-quantity pack.
// grid = b(4)*d(128)*strip(11) = 5632 blocks, 256 threads, smem 54,432 B.
// ---------------------------------------------------------------------------
__global__ void __launch_bounds__(256, 4)
fused_wh(const float* __restrict__ X, const float* __restrict__ Y) {
    extern __shared__ float sm[];
    float*  xs  = sm;                          // [NIN][XP]
    float*  ys  = sm + NIN * XP;               // [NIN][XP]
    float4* rw4 = (float4*)(sm + 2 * NIN * XP);// [NIN][RP]

    const int s  = blockIdx.x % NSTRIP;
    const int d  = (blockIdx.x / NSTRIP) % DD;
    const int b  = blockIdx.x / (NSTRIP * DD);
    const int h0 = s * STRIP;
    const int nout = min(STRIP, WO - h0);      // 12 (last strip: 2)
    const int nin  = nout + 6;                 // 18 (last strip: 8)
    const int tid  = threadIdx.x;

    const size_t gbase = ((size_t)(b * DD + d) * HH + h0) * WW;
    for (int i = tid; i < nin * 32; i += 256) {
        const int r = i >> 5, v = (i & 31) << 2;
        const float4 xv = *(const float4*)(X + gbase + (size_t)r * WW + v);
        const float4 yv = *(const float4*)(Y + gbase + (size_t)r * WW + v);
        *(float4*)(xs + r * XP + v) = xv;
        *(float4*)(ys + r * XP + v) = yv;
    }
    __syncthreads();

    // --- W-direction sliding sums: (sx, sy, sxx+syy, sxy) ---
    {
        const int njobs = nin * 8;
        for (int job = tid; job < njobs; job += 256) {
            const int r   = job % nin;
            const int ch  = job / nin;
            const int wst = ch * 16;
            const int nw  = (ch == 7) ? 10 : 16;

            float xv[24], yv[24];
#pragma unroll
            for (int k = 0; k < 6; k++) {
                if (wst + 4 * k < WW) {
                    const float4 xq = *(const float4*)(xs + r * XP + wst + 4 * k);
                    const float4 yq = *(const float4*)(ys + r * XP + wst + 4 * k);
                    xv[4*k] = xq.x; xv[4*k+1] = xq.y; xv[4*k+2] = xq.z; xv[4*k+3] = xq.w;
                    yv[4*k] = yq.x; yv[4*k+1] = yq.y; yv[4*k+2] = yq.z; yv[4*k+3] = yq.w;
                } else {
#pragma unroll
                    for (int u = 0; u < 4; u++) { xv[4*k+u] = 0.f; yv[4*k+u] = 0.f; }
                }
            }

            float s0 = 0.f, s1 = 0.f, s2 = 0.f, s4 = 0.f;
#pragma unroll
            for (int j = 0; j < 6; j++) {
                s0 += xv[j]; s1 += yv[j];
                s2 += xv[j] * xv[j] + yv[j] * yv[j];
                s4 += xv[j] * yv[j];
            }
#pragma unroll
            for (int o = 0; o < 16; o++) {
                if (o < nw) {
                    s0 += xv[o + 6]; s1 += yv[o + 6];
                    s2 += xv[o + 6] * xv[o + 6] + yv[o + 6] * yv[o + 6];
                    s4 += xv[o + 6] * yv[o + 6];
                    rw4[r * RP + wst + o] = make_float4(s0, s1, s2, s4);
                    s0 -= xv[o]; s1 -= yv[o];
                    s2 -= xv[o] * xv[o] + yv[o] * yv[o];
                    s4 -= xv[o] * yv[o];
                }
            }
        }
    }
    __syncthreads();

    // --- H-direction sliding sums with 7-deep register history ---
    for (int w = tid; w < WO; w += 256) {
        const size_t obase = ((size_t)(b * DD + d) * WO + h0) * GP + w;
        float4 hist[7];
        float4 acc = make_float4(0.f, 0.f, 0.f, 0.f);
#pragma unroll
        for (int r = 0; r < NIN; r++) {
            if (r < nin) {
                const float4 v = rw4[r * RP + w];
                acc.x += v.x; acc.y += v.y; acc.z += v.z; acc.w += v.w;
                if (r >= 6) {
                    const int o = r - 6;
                    g2q[obase + (size_t)o * GP] = acc;
                    const float4 h7 = hist[o % 7];
                    acc.x -= h7.x; acc.y -= h7.y; acc.z -= h7.z; acc.w -= h7.w;
                }
                hist[r % 7] = v;
            }
        }
    }
}

// ---------------------------------------------------------------------------
// Kernel B: branch-free D window sums + SSIM (SMEM ring, paired division).
// ---------------------------------------------------------------------------
template <int NST>
__device__ __forceinline__ float run_chunk(size_t base, float C1, float C2,
                                           float4* ring) {
    constexpr float inv = 1.0f / 343.0f;
    constexpr float cov = 343.0f / 342.0f;
    const size_t ds = (size_t)WO * GP;

    float4 acc = make_float4(0.f, 0.f, 0.f, 0.f);
    float  local = 0.f;
    float  pn = 0.f, pd = 1.f;

#pragma unroll
    for (int j = 0; j < NST; j++) {
        const float4 v = __ldg(&g2q[base + (size_t)j * ds]);
        acc.x += v.x; acc.y += v.y; acc.z += v.z; acc.w += v.w;
        if (j >= 6) {
            const float ux  = acc.x * inv;      // mean x
            const float uy  = acc.y * inv;      // mean y
            const float uss = acc.z * inv;      // mean (x^2 + y^2)
            const float uxy = acc.w * inv;      // mean xy
            const float sq  = ux * ux + uy * uy;
            const float vxy = cov * (uxy - ux * uy);
            const float vs  = cov * (uss - sq);           // vx + vy
            const float A1 = 2.f * ux * uy + C1;
            const float A2 = 2.f * vxy + C2;
            const float B1 = sq + C1;
            const float B2 = vs + C2;
            const float n  = A1 * A2;
            const float dn = B1 * B2;
            if (((j - 6) & 1) == 0) {
                pn = n; pd = dn;
            } else {
                local += __fdividef(n * pd + pn * dn, dn * pd);
            }
            const float4 o4 = ring[(j - 6) % 7];   // written 6 steps ago
            acc.x -= o4.x; acc.y -= o4.y; acc.z -= o4.z; acc.w -= o4.w;
        }
        ring[j % 7] = v;
    }
    return local;
}

__global__ void __launch_bounds__(256, 5)
pass_d_ssim(const float* __restrict__ dr, float* __restrict__ out) {
    __shared__ float4 ringbuf[256 * 7];   // 28,672 B; per-thread stride 7 (28 words)
    __shared__ double red[256];

    const int tid   = threadIdx.x;
    const int idx   = blockIdx.x * 256 + tid;
    const int total = 8 * BATCH * WO * WO;

    float4* ring = &ringbuf[tid * 7];

    float local = 0.f;
    if (idx < total) {
        const int w = idx % WO;
        const int h = (idx / WO) % WO;
        const int b = (idx / (WO * WO)) % BATCH;
        const int c = idx / (WO * WO * BATCH);

        const int d0 = c * 16;                 // chunks 0..6: 16 outs, chunk 7: 10

        const float r  = __ldg(&dr[b]);
        const float C1 = (0.01f * r) * (0.01f * r);
        const float C2 = (0.03f * r) * (0.03f * r);

        const size_t base = ((size_t)(b * DD + d0) * WO + h) * GP + w;

        if (c < 7) local = run_chunk<22>(base, C1, C2, ring);   // 16 outputs
        else       local = run_chunk<16>(base, C1, C2, ring);   // 10 outputs
    }

    red[tid] = (double)local;
    __syncthreads();
#pragma unroll
    for (int s = 128; s > 0; s >>= 1) {
        if (tid < s) red[tid] += red[tid + s];
        __syncthreads();
    }

    __shared__ bool is_last;
    if (tid == 0) {
        g_part[blockIdx.x] = red[0];
        __threadfence();
        const unsigned int t = atomicAdd(&g_ctr, 1u);
        is_last = (t == gridDim.x - 1);
    }
    __syncthreads();

    if (is_last) {
        __threadfence();
        double v = 0.0;
        for (int i = tid; i < (int)gridDim.x; i += 256) v += g_part[i];
        red[tid] = v;
        __syncthreads();
#pragma unroll
        for (int s = 128; s > 0; s >>= 1) {
            if (tid < s) red[tid] += red[tid + s];
            __syncthreads();
        }
        if (tid == 0) {
            const double cnt = (double)BATCH * WO * WO * WO;
            out[0] = (float)(red[0] / cnt);
            atomicExch(&g_ctr, 0u);   // reset for next graph replay
        }
    }
}

extern "C" void kernel_launch(void* const* d_in, const int* in_sizes, int n_in,
                              void* d_out, int out_size) {
    const float* X  = (const float*)d_in[0];
    const float* Y  = (const float*)d_in[1];
    const float* dr = (const float*)d_in[2];
    float* out = (float*)d_out;

    const int smemA = (2 * NIN * XP) * (int)sizeof(float) + NIN * RP * (int)sizeof(float4); // 54,432 B
    cudaFuncSetAttribute(fused_wh, cudaFuncAttributeMaxDynamicSharedMemorySize, smemA);

    fused_wh<<<BATCH * DD * NSTRIP, 256, smemA>>>(X, Y);

    const int totalB = 8 * BATCH * WO * WO;          // 476,288
    const int nblocksB = (totalB + 255) / 256;       // 1861
    pass_d_ssim<<<nblocksB, 256>>>(dr, out);
}

// round 16
// speedup vs baseline: 1.3532x; 1.0034x over previous
#include <cuda_runtime.h>

// 3D SSIM, B=4, 128^3, WIN=7 separable box -> 122^3, mean.
// Intermediate: ONE float4 per voxel (sx, sy, sxx+syy, sxy), pitch 128.
// R13 structure + packed f32x2 arithmetic (add.rn.f32x2 / fma.rn.f32x2) in the
// hot accumulate/subtract paths of both kernels.

#define BATCH 4
#define DD 128
#define HH 128
#define WW 128
#define WO  122
#define WIN 7

#define STRIP  14
#define NSTRIP 9
#define XP 132
#define RP 123
#define GP 128            // g2 row pitch (elements)

typedef unsigned long long u64;

__device__ float4 g2q[62464 * GP];     // (b,d,h) rows, pitch 128 -> 128 MB
__device__ double g_part[2048];
__device__ unsigned int g_ctr = 0;

// ---- packed f32x2 helpers -------------------------------------------------
__device__ __forceinline__ u64 add2(u64 a, u64 b) {
    u64 r; asm("add.rn.f32x2 %0, %1, %2;" : "=l"(r) : "l"(a), "l"(b)); return r;
}
__device__ __forceinline__ u64 fma2(u64 a, u64 b, u64 c) {
    u64 r; asm("fma.rn.f32x2 %0, %1, %2, %3;" : "=l"(r) : "l"(a), "l"(b), "l"(c)); return r;
}
__device__ __forceinline__ u64 pack2(float lo, float hi) {
    u64 r; asm("mov.b64 %0, {%1, %2};" : "=l"(r) : "f"(lo), "f"(hi)); return r;
}
__device__ __forceinline__ void unpack2(u64 v, float& lo, float& hi) {
    asm("mov.b64 {%0, %1}, %2;" : "=f"(lo), "=f"(hi) : "l"(v));
}

// ---------------------------------------------------------------------------
// Kernel A: fused W+H box sums, 4-quantity pack (R8/R13 form, packed H-phase).
// grid = 4608 blocks, 256 threads, smem 60,480 B, 3 blocks/SM.
// ---------------------------------------------------------------------------
__global__ void __launch_bounds__(256, 3)
fused_wh(const float* __restrict__ X, const float* __restrict__ Y) {
    extern __shared__ float sm[];
    float*  xs  = sm;                         // [20][XP]
    float*  ys  = sm + 20 * XP;               // [20][XP]
    float4* rw4 = (float4*)(sm + 40 * XP);    // [20][RP]

    const int s  = blockIdx.x % NSTRIP;
    const int d  = (blockIdx.x / NSTRIP) % DD;
    const int b  = blockIdx.x / (NSTRIP * DD);
    const int h0 = s * STRIP;
    const int nout = min(STRIP, WO - h0);     // 14 (last strip: 10)
    const int nin  = nout + 6;                // 20 (last strip: 16)
    const int tid  = threadIdx.x;

    const size_t gbase = ((size_t)(b * DD + d) * HH + h0) * WW;
    for (int i = tid; i < nin * 32; i += 256) {
        const int r = i >> 5, v = (i & 31) << 2;
        const float4 xv = *(const float4*)(X + gbase + (size_t)r * WW + v);
        const float4 yv = *(const float4*)(Y + gbase + (size_t)r * WW + v);
        *(float4*)(xs + r * XP + v) = xv;
        *(float4*)(ys + r * XP + v) = yv;
    }
    __syncthreads();

    // --- W-direction sliding sums: (sx, sy, sxx+syy, sxy) ---
    {
        const int njobs = nin * 8;
        for (int job = tid; job < njobs; job += 256) {
            const int r   = job % nin;
            const int ch  = job / nin;
            const int wst = ch * 16;
            const int nw  = (ch == 7) ? 10 : 16;

            float xv[24], yv[24];
#pragma unroll
            for (int k = 0; k < 6; k++) {
                if (wst + 4 * k < WW) {
                    const float4 xq = *(const float4*)(xs + r * XP + wst + 4 * k);
                    const float4 yq = *(const float4*)(ys + r * XP + wst + 4 * k);
                    xv[4*k] = xq.x; xv[4*k+1] = xq.y; xv[4*k+2] = xq.z; xv[4*k+3] = xq.w;
                    yv[4*k] = yq.x; yv[4*k+1] = yq.y; yv[4*k+2] = yq.z; yv[4*k+3] = yq.w;
                } else {
#pragma unroll
                    for (int u = 0; u < 4; u++) { xv[4*k+u] = 0.f; yv[4*k+u] = 0.f; }
                }
            }

            float s0 = 0.f, s1 = 0.f, s2 = 0.f, s4 = 0.f;
#pragma unroll
            for (int j = 0; j < 6; j++) {
                s0 += xv[j]; s1 += yv[j];
                s2 += xv[j] * xv[j] + yv[j] * yv[j];
                s4 += xv[j] * yv[j];
            }
#pragma unroll
            for (int o = 0; o < 16; o++) {
                if (o < nw) {
                    s0 += xv[o + 6]; s1 += yv[o + 6];
                    s2 += xv[o + 6] * xv[o + 6] + yv[o + 6] * yv[o + 6];
                    s4 += xv[o + 6] * yv[o + 6];
                    rw4[r * RP + wst + o] = make_float4(s0, s1, s2, s4);
                    s0 -= xv[o]; s1 -= yv[o];
                    s2 -= xv[o] * xv[o] + yv[o] * yv[o];
                    s4 -= xv[o] * yv[o];
                }
            }
        }
    }
    __syncthreads();

    // --- H-direction sliding sums, packed f32x2 accumulate/subtract ---
    {
        const u64 NEG1 = pack2(-1.f, -1.f);
        for (int w = tid; w < WO; w += 256) {
            const size_t obase = ((size_t)(b * DD + d) * WO + h0) * GP + w;
            ulonglong2 hist[7];
            u64 a01 = 0ull, a23 = 0ull;       // packed (0,0)
#pragma unroll
            for (int r = 0; r < 20; r++) {
                if (r < nin) {
                    const ulonglong2 v = *(const ulonglong2*)&rw4[r * RP + w];
                    a01 = add2(a01, v.x);
                    a23 = add2(a23, v.y);
                    if (r >= 6) {
                        const int o = r - 6;
                        ulonglong2 st; st.x = a01; st.y = a23;
                        *(ulonglong2*)&g2q[obase + (size_t)o * GP] = st;
                        const ulonglong2 h7 = hist[o % 7];
                        a01 = fma2(h7.x, NEG1, a01);
                        a23 = fma2(h7.y, NEG1, a23);
                    }
                    hist[r % 7] = v;
                }
            }
        }
    }
}

// ---------------------------------------------------------------------------
// Kernel B: D window sums + SSIM (SMEM ulonglong2 ring, packed f32x2, paired div).
// ---------------------------------------------------------------------------
template <int NST>
__device__ __forceinline__ float run_chunk(size_t base, float C1, float C2,
                                           ulonglong2* ring) {
    constexpr float inv = 1.0f / 343.0f;
    constexpr float cov = 343.0f / 342.0f;
    const size_t ds = (size_t)WO * GP;
    const u64 NEG1 = pack2(-1.f, -1.f);

    u64 a01 = 0ull, a23 = 0ull;
    float local = 0.f;
    float pn = 0.f, pd = 1.f;

#pragma unroll
    for (int j = 0; j < NST; j++) {
        const ulonglong2 v = __ldg((const ulonglong2*)&g2q[base + (size_t)j * ds]);
        a01 = add2(a01, v.x);
        a23 = add2(a23, v.y);
        if (j >= 6) {
            float ax, ay, az, aw;
            unpack2(a01, ax, ay);
            unpack2(a23, az, aw);
            const float ux  = ax * inv;      // mean x
            const float uy  = ay * inv;      // mean y
            const float uss = az * inv;      // mean (x^2 + y^2)
            const float uxy = aw * inv;      // mean xy
            const float sq  = ux * ux + uy * uy;
            const float vxy = cov * (uxy - ux * uy);
            const float vs  = cov * (uss - sq);           // vx + vy
            const float A1 = 2.f * ux * uy + C1;
            const float A2 = 2.f * vxy + C2;
            const float B1 = sq + C1;
            const float B2 = vs + C2;
            const float n  = A1 * A2;
            const float dn = B1 * B2;
            if (((j - 6) & 1) == 0) {
                pn = n; pd = dn;
            } else {
                local += __fdividef(n * pd + pn * dn, dn * pd);
            }
            const ulonglong2 o4 = ring[(j - 6) % 7];   // written 6 steps ago
            a01 = fma2(o4.x, NEG1, a01);
            a23 = fma2(o4.y, NEG1, a23);
        }
        ring[j % 7] = v;
    }
    return local;
}

__global__ void __launch_bounds__(256, 5)
pass_d_ssim(const float* __restrict__ dr, float* __restrict__ out) {
    __shared__ ulonglong2 ringbuf[256 * 7];   // 28,672 B
    __shared__ double red[256];

    const int tid   = threadIdx.x;
    const int idx   = blockIdx.x * 256 + tid;
    const int total = 8 * BATCH * WO * WO;

    ulonglong2* ring = &ringbuf[tid * 7];

    float local = 0.f;
    if (idx < total) {
        const int w = idx % WO;
        const int h = (idx / WO) % WO;
        const int b = (idx / (WO * WO)) % BATCH;
        const int c = idx / (WO * WO * BATCH);

        const int d0 = c * 16;                 // chunks 0..6: 16 outs, chunk 7: 10

        const float r  = __ldg(&dr[b]);
        const float C1 = (0.01f * r) * (0.01f * r);
        const float C2 = (0.03f * r) * (0.03f * r);

        const size_t base = ((size_t)(b * DD + d0) * WO + h) * GP + w;

        if (c < 7) local = run_chunk<22>(base, C1, C2, ring);   // 16 outputs
        else       local = run_chunk<16>(base, C1, C2, ring);   // 10 outputs
    }

    red[tid] = (double)local;
    __syncthreads();
#pragma unroll
    for (int s = 128; s > 0; s >>= 1) {
        if (tid < s) red[tid] += red[tid + s];
        __syncthreads();
    }

    __shared__ bool is_last;
    if (tid == 0) {
        g_part[blockIdx.x] = red[0];
        __threadfence();
        const unsigned int t = atomicAdd(&g_ctr, 1u);
        is_last = (t == gridDim.x - 1);
    }
    __syncthreads();

    if (is_last) {
        __threadfence();
        double v = 0.0;
        for (int i = tid; i < (int)gridDim.x; i += 256) v += g_part[i];
        red[tid] = v;
        __syncthreads();
#pragma unroll
        for (int s = 128; s > 0; s >>= 1) {
            if (tid < s) red[tid] += red[tid + s];
            __syncthreads();
        }
        if (tid == 0) {
            const double cnt = (double)BATCH * WO * WO * WO;
            out[0] = (float)(red[0] / cnt);
            atomicExch(&g_ctr, 0u);   // reset for next graph replay
        }
    }
}

extern "C" void kernel_launch(void* const* d_in, const int* in_sizes, int n_in,
                              void* d_out, int out_size) {
    const float* X  = (const float*)d_in[0];
    const float* Y  = (const float*)d_in[1];
    const float* dr = (const float*)d_in[2];
    float* out = (float*)d_out;

    const int smemA = (40 * XP) * (int)sizeof(float) + 20 * RP * (int)sizeof(float4); // 60,480 B
    cudaFuncSetAttribute(fused_wh, cudaFuncAttributeMaxDynamicSharedMemorySize, smemA);

    fused_wh<<<BATCH * DD * NSTRIP, 256, smemA>>>(X, Y);

    const int totalB = 8 * BATCH * WO * WO;          // 476,288
    const int nblocksB = (totalB + 255) / 256;       // 1861
    pass_d_ssim<<<nblocksB, 256>>>(dr, out);
}